// round 16
// baseline (speedup 1.0000x reference)
#include <cuda_runtime.h>
#include <cstdint>

// ---------------------------------------------------------------------------
// GAT hierarchical 2-layer. R16 = R15 (117.2us proven) with:
//  (1) attn512 logit phase: quarter-row per warp + butterfly multi-reduce +
//      smem combine (logit smem wavefronts 640 -> 160 per block),
//  (2) prepN and prepQP fused into ONE kernel (QP made self-contained by
//      computing P1 = W1 @ a1 in smem, no N dependency).
// attn128 / GEMMs byte-identical to R15.
// ---------------------------------------------------------------------------

// scratch layout (floats)
static constexpr size_t OFF_Y1 = 0;                        // [10240,512]
static constexpr size_t OFF_Y0 = OFF_Y1 + 10240ull * 512;  // [1024,512]
static constexpr size_t OFF_U  = OFF_Y0 + 1024ull * 512;   // [1024,2048]
static constexpr size_t OFF_H  = OFF_U  + 1024ull * 2048;  // [1024,512]
static constexpr size_t OFF_P0 = OFF_H  + 1024ull * 512;   // P0s[512],P0n[512]
static constexpr size_t OFF_Q  = OFF_P0 + 1024;            // Qs[2048],Qn[2048]
static constexpr size_t OFF_N  = OFF_Q  + 4096;            // N[4][512][128]
static constexpr size_t SCRATCH_FLOATS = OFF_N + 4ull * 512 * 128;

__device__ float g_scratch[SCRATCH_FLOATS];

static __device__ __forceinline__ float4 ldg4(const float* p) {
    return __ldg((const float4*)p);
}
static __device__ __forceinline__ float dot4(float4 a, float4 b, float acc) {
    acc = fmaf(a.x, b.x, acc);
    acc = fmaf(a.y, b.y, acc);
    acc = fmaf(a.z, b.z, acc);
    acc = fmaf(a.w, b.w, acc);
    return acc;
}
static __device__ __forceinline__ uint32_t smem_u32(const void* p) {
    return (uint32_t)__cvta_generic_to_shared(p);
}
static __device__ __forceinline__ void mbar_init(uint32_t mbar, uint32_t cnt) {
    asm volatile("mbarrier.init.shared.b64 [%0], %1;" :: "r"(mbar), "r"(cnt) : "memory");
}
static __device__ __forceinline__ void mbar_expect_tx(uint32_t mbar, uint32_t bytes) {
    asm volatile("mbarrier.arrive.expect_tx.shared.b64 _, [%0], %1;"
                 :: "r"(mbar), "r"(bytes) : "memory");
}
static __device__ __forceinline__ void bulk_g2s(uint32_t dst, const void* src,
                                                uint32_t bytes, uint32_t mbar) {
    asm volatile("cp.async.bulk.shared::cluster.global.mbarrier::complete_tx::bytes "
                 "[%0], [%1], %2, [%3];"
                 :: "r"(dst), "l"(src), "r"(bytes), "r"(mbar) : "memory");
}
static __device__ __forceinline__ void mbar_wait(uint32_t mbar, uint32_t parity) {
    asm volatile(
        "{\n\t.reg .pred P;\n"
        "W_%=:\n\t"
        "mbarrier.try_wait.parity.shared.b64 P, [%0], %1;\n\t"
        "@P bra D_%=;\n\t"
        "bra W_%=;\n"
        "D_%=:\n\t}"
        :: "r"(mbar), "r"(parity) : "memory");
}
static __device__ __forceinline__ float4 lds4(const float* p) {
    float4 v;
    asm volatile("ld.shared.v4.f32 {%0,%1,%2,%3}, [%4];"
                 : "=f"(v.x), "=f"(v.y), "=f"(v.z), "=f"(v.w)
                 : "r"(smem_u32(p)));
    return v;
}

// butterfly multi-reduce: (p0..p3 per lane) -> lane l (l<4) holds full sum of
// head l over all 32 lanes. 6 shfl. Proven in R10/R15.
static __device__ __forceinline__ float butterfly4(float p0, float p1,
                                                   float p2, float p3, int lane)
{
    bool b0 = (lane & 1);
    float send = b0 ? p0 : p1;
    float recv = __shfl_xor_sync(0xffffffffu, send, 1);
    float q01 = (b0 ? p1 : p0) + recv;
    send = b0 ? p2 : p3;
    recv = __shfl_xor_sync(0xffffffffu, send, 1);
    float q23 = (b0 ? p3 : p2) + recv;

    bool b1 = (lane & 2);
    send = b1 ? q01 : q23;
    recv = __shfl_xor_sync(0xffffffffu, send, 2);
    float r = (b1 ? q23 : q01) + recv;

    r += __shfl_xor_sync(0xffffffffu, r, 4);
    r += __shfl_xor_sync(0xffffffffu, r, 8);
    r += __shfl_xor_sync(0xffffffffu, r, 16);
    return r;
}

// ---------------------------------------------------------------------------
// Fused prep: blocks [0,256) = prepN 32x32 tiles; blocks [256,272) = Q
// (self-contained via P1 = W1@a1 in smem); blocks [272,276) = P0.
// 256 threads everywhere.
// ---------------------------------------------------------------------------
__global__ __launch_bounds__(256)
void prep_kernel(const float* __restrict__ W0, const float* __restrict__ W1,
                 const float* __restrict__ a0s, const float* __restrict__ a0n,
                 const float* __restrict__ a1s, const float* __restrict__ a1n,
                 float* __restrict__ Nmat, float* __restrict__ Q,
                 float* __restrict__ P0)
{
    const int b = blockIdx.x;
    const int tid = threadIdx.x;

    if (b < 256) {
        // prepN tile: z = b>>4, y = (b>>2)&3, x = b&3
        const int z = b >> 4;
        const int hp = z >> 2, h = z & 3;
        const float* A = W0 + h * 128;
        const float* B = W1 + (size_t)(h * 128) * 512 + hp * 128;
        float* C = Nmat + (size_t)hp * 65536 + (size_t)(h * 128) * 128;

        const int M0 = ((b >> 2) & 3) * 32;
        const int N0 = (b & 3) * 32;
        const int tx = tid & 15;
        const int ty = tid >> 4;

        __shared__ float As[16][32];
        __shared__ float Bs[16][32];

        float acc[2][2] = {{0.f, 0.f}, {0.f, 0.f}};

        for (int k0 = 0; k0 < 128; k0 += 16) {
            if (tid < 128) {
                int r = tid >> 2, c4 = (tid & 3) * 4;
                float4 av = *(const float4*)(A + (size_t)(M0 + r) * 512 + k0 + c4);
                As[c4 + 0][r] = av.x;
                As[c4 + 1][r] = av.y;
                As[c4 + 2][r] = av.z;
                As[c4 + 3][r] = av.w;
            } else {
                int t = tid - 128;
                int r = t >> 3, c4 = (t & 7) * 4;
                float4 bv = *(const float4*)(B + (size_t)(k0 + r) * 512 + N0 + c4);
                *(float4*)&Bs[r][c4] = bv;
            }
            __syncthreads();
            #pragma unroll
            for (int k = 0; k < 16; k++) {
                float a0 = As[k][ty * 2], a1 = As[k][ty * 2 + 1];
                float b0 = Bs[k][tx * 2], b1 = Bs[k][tx * 2 + 1];
                acc[0][0] = fmaf(a0, b0, acc[0][0]);
                acc[0][1] = fmaf(a0, b1, acc[0][1]);
                acc[1][0] = fmaf(a1, b0, acc[1][0]);
                acc[1][1] = fmaf(a1, b1, acc[1][1]);
            }
            __syncthreads();
        }
        #pragma unroll
        for (int i = 0; i < 2; i++)
            #pragma unroll
            for (int j = 0; j < 2; j++)
                C[(size_t)(M0 + ty * 2 + i) * 128 + N0 + tx * 2 + j] = acc[i][j];
    } else if (b < 272) {
        // Q block (hp, h): half 0 -> Qs (a1s), half 1 -> Qn (a1n)
        const int bp = b - 256;
        const int hp = bp >> 2, h = bp & 3;
        const int half = tid >> 7, l = tid & 127;

        __shared__ float sa[2][128];
        __shared__ float p1[2][128];

        const float* a1 = half ? a1n : a1s;
        sa[half][l] = __ldg(a1 + hp * 128 + l);
        __syncthreads();

        // P1[l] = sum_d' W1[(h*128+l), hp*128+d'] * a1[hp,d']
        const float* w1row = W1 + (size_t)(h * 128 + l) * 512 + hp * 128;
        float acc = 0.f;
        #pragma unroll 4
        for (int d = 0; d < 128; d++) acc = fmaf(w1row[d], sa[half][d], acc);
        p1[half][l] = acc;
        __syncthreads();

        // Q[hp*512 + h*128 + l] = sum_d W0[l, h*128+d] * P1[d]
        const float* w0row = W0 + (size_t)l * 512 + h * 128;
        float q = 0.f;
        #pragma unroll 4
        for (int d = 0; d < 128; d++) q = fmaf(w0row[d], p1[half][d], q);
        (half ? (Q + 2048) : Q)[hp * 512 + h * 128 + l] = q;
    } else {
        // P0 block: t in [0,512) = (h,f); half 0 -> P0s, half 1 -> P0n
        const int half = tid >> 7, l = tid & 127;
        const int t = (b - 272) * 128 + l;
        const int h = t >> 7, f = t & 127;
        const float* wrow = W0 + (size_t)f * 512 + h * 128;
        const float* a = (half ? a0n : a0s) + h * 128;
        float acc = 0.f;
        #pragma unroll 4
        for (int d = 0; d < 128; d++) acc = fmaf(wrow[d], __ldg(a + d), acc);
        (half ? (P0 + 512) : P0)[t] = acc;
    }
}

// ---------------------------------------------------------------------------
// fp32 GEMM: 64x64 tile, BK=16, 256 threads, 4x4/thread, reg double-buffer.
// Byte-identical to R6/R15.
// ---------------------------------------------------------------------------
__global__ __launch_bounds__(256)
void gemm_kernel(const float* __restrict__ A, const float* __restrict__ B,
                 float* __restrict__ C,
                 int K, int lda, int ldb, int ldc,
                 int offA, int offB, int offC)
{
    A += (size_t)blockIdx.z * offA;
    B += (size_t)blockIdx.z * offB;
    C += (size_t)blockIdx.z * offC;

    const int row0 = blockIdx.y * 64;
    const int col0 = blockIdx.x * 64;
    const int tx = threadIdx.x;
    const int ty = threadIdx.y;
    const int tid = ty * 16 + tx;

    __shared__ float As[16][64];
    __shared__ float Bs[16][64];

    const int ar = tid >> 2;
    const int ac = (tid & 3) * 4;
    const int br = tid >> 4;
    const int bc = (tid & 15) * 4;

    float acc[4][4];
    #pragma unroll
    for (int i = 0; i < 4; i++)
        #pragma unroll
        for (int j = 0; j < 4; j++) acc[i][j] = 0.f;

    const int nt = K >> 4;
    float4 av = *(const float4*)(A + (size_t)(row0 + ar) * lda + ac);
    float4 bv = *(const float4*)(B + (size_t)br * ldb + col0 + bc);

    for (int i = 0; i < nt; i++) {
        As[ac + 0][ar] = av.x;
        As[ac + 1][ar] = av.y;
        As[ac + 2][ar] = av.z;
        As[ac + 3][ar] = av.w;
        *(float4*)&Bs[br][bc] = bv;
        __syncthreads();

        if (i + 1 < nt) {
            int k0 = (i + 1) << 4;
            av = *(const float4*)(A + (size_t)(row0 + ar) * lda + k0 + ac);
            bv = *(const float4*)(B + (size_t)(k0 + br) * ldb + col0 + bc);
        }

        #pragma unroll
        for (int k = 0; k < 16; k++) {
            float4 a4 = *(const float4*)&As[k][ty * 4];
            float4 b4 = *(const float4*)&Bs[k][tx * 4];
            float a[4] = {a4.x, a4.y, a4.z, a4.w};
            float b[4] = {b4.x, b4.y, b4.z, b4.w};
            #pragma unroll
            for (int ii = 0; ii < 4; ii++)
                #pragma unroll
                for (int jj = 0; jj < 4; jj++)
                    acc[ii][jj] = fmaf(a[ii], b[jj], acc[ii][jj]);
        }
        __syncthreads();
    }

    #pragma unroll
    for (int i = 0; i < 4; i++) {
        float4 o = {acc[i][0], acc[i][1], acc[i][2], acc[i][3]};
        *(float4*)(C + (size_t)(row0 + ty * 4 + i) * ldc + col0 + tx * 4) = o;
    }
}

// ---------------------------------------------------------------------------
// F=128 attention, both levels fused. Byte-identical to R15 (the winner).
// ---------------------------------------------------------------------------
__global__ __launch_bounds__(128)
void attn128_kernel(const float* __restrict__ h0, const float* __restrict__ h1,
                    const float* __restrict__ h2,
                    const float* __restrict__ Ws, const float* __restrict__ Wn,
                    float* __restrict__ y1, float* __restrict__ y0, int G1)
{
    __shared__ float sxn[25 * 128];
    __shared__ float slog[26 * 4];
    __shared__ float salpha[25 * 4];
    __shared__ uint64_t mbar_s;

    const int b = blockIdx.x;
    const bool big = b < G1;
    const int g = big ? b : b - G1;
    const int E = big ? 25 : 10;
    const float* gxn = big ? (h2 + (size_t)g * 25 * 128) : (h1 + (size_t)g * 10 * 128);
    const float* gxs = big ? (h1 + (size_t)g * 128) : (h0 + (size_t)g * 128);
    float* gy = (big ? y1 : y0) + (size_t)g * 512;

    const int tid  = threadIdx.x;
    const int w    = tid >> 5;
    const int lane = tid & 31;
    const uint32_t mbar = smem_u32(&mbar_s);

    if (tid == 0) {
        mbar_init(mbar, 1);
        asm volatile("fence.proxy.async.shared::cta;" ::: "memory");
    }
    __syncthreads();
    if (tid == 0) {
        mbar_expect_tx(mbar, (uint32_t)(E * 128 * 4));
        bulk_g2s(smem_u32(sxn), gxn, (uint32_t)(E * 128 * 4), mbar);
    }

    float4 wn0 = ldg4(Wn + 0 * 128 + 4 * lane);
    float4 wn1 = ldg4(Wn + 1 * 128 + 4 * lane);
    float4 wn2 = ldg4(Wn + 2 * 128 + 4 * lane);
    float4 wn3 = ldg4(Wn + 3 * 128 + 4 * lane);

    if (w == 0) {
        float4 xv = ldg4(gxs + 4 * lane);
        float p0 = dot4(xv, ldg4(Ws + 0 * 128 + 4 * lane), 0.f);
        float p1 = dot4(xv, ldg4(Ws + 1 * 128 + 4 * lane), 0.f);
        float p2 = dot4(xv, ldg4(Ws + 2 * 128 + 4 * lane), 0.f);
        float p3 = dot4(xv, ldg4(Ws + 3 * 128 + 4 * lane), 0.f);
        float r = butterfly4(p0, p1, p2, p3, lane);
        if (lane < 4) slog[E * 4 + lane] = r;
    }

    mbar_wait(mbar, 0);

    for (int e = w; e < E; e += 4) {
        float4 xv = lds4(&sxn[e * 128 + 4 * lane]);
        float p0 = dot4(xv, wn0, 0.f);
        float p1 = dot4(xv, wn1, 0.f);
        float p2 = dot4(xv, wn2, 0.f);
        float p3 = dot4(xv, wn3, 0.f);
        float r = butterfly4(p0, p1, p2, p3, lane);
        if (lane < 4) slog[e * 4 + lane] = r;
    }
    __syncthreads();

    {
        float es = slog[E * 4 + w];
        float v;
        if (lane < E) {
            float l = es + slog[lane * 4 + w];
            v = (l >= 0.f) ? l : 0.2f * l;
        } else {
            v = -3.4e38f;
        }
        float m = v;
        #pragma unroll
        for (int o = 16; o; o >>= 1) m = fmaxf(m, __shfl_xor_sync(0xffffffffu, m, o));
        float p = (lane < E) ? __expf(v - m) : 0.f;
        float sum = p;
        #pragma unroll
        for (int o = 16; o; o >>= 1) sum += __shfl_xor_sync(0xffffffffu, sum, o);
        if (lane < E) salpha[lane * 4 + w] = p / sum;
    }
    __syncthreads();

    float acc0 = 0.f, acc1 = 0.f, acc2 = 0.f, acc3 = 0.f;
    for (int e = 0; e < E; e++) {
        float4 al = lds4(&salpha[e * 4]);
        float val = sxn[e * 128 + tid];
        acc0 = fmaf(al.x, val, acc0);
        acc1 = fmaf(al.y, val, acc1);
        acc2 = fmaf(al.z, val, acc2);
        acc3 = fmaf(al.w, val, acc3);
    }
    gy[0 * 128 + tid] = acc0;
    gy[1 * 128 + tid] = acc1;
    gy[2 * 128 + tid] = acc2;
    gy[3 * 128 + tid] = acc3;
}

// ---------------------------------------------------------------------------
// F=512, E=10 layer-1 attention. NEW logit phase: warp w reads only its
// quarter-row (one LDS.128/lane), computes partials for ALL 4 heads against
// quarter-weight registers, butterfly-reduces, deposits to smem; softmax
// combines the 4 warp-partials. Logit smem wavefronts: 640 -> 160 per block.
// ---------------------------------------------------------------------------
__global__ __launch_bounds__(128)
void attn512_kernel(const float* __restrict__ xs, const float* __restrict__ xn,
                    const float* __restrict__ Ws, const float* __restrict__ Wn,
                    float* __restrict__ y)
{
    constexpr int E = 10, F = 512;
    __shared__ float sxn[E * F];
    __shared__ float sredN[E][4][4];   // [row][warp][head]
    __shared__ float sredS[4][4];      // [warp][head]
    __shared__ float salpha[E * 4];
    __shared__ uint64_t mbar_s;

    const int g    = blockIdx.x;
    const int tid  = threadIdx.x;
    const int w    = tid >> 5;
    const int lane = tid & 31;
    const uint32_t mbar = smem_u32(&mbar_s);
    const float* gxn = xn + (size_t)g * E * F;
    const float* gxs = xs + (size_t)g * F;

    if (tid == 0) {
        mbar_init(mbar, 1);
        asm volatile("fence.proxy.async.shared::cta;" ::: "memory");
    }
    __syncthreads();
    if (tid == 0) {
        mbar_expect_tx(mbar, E * F * 4);
        bulk_g2s(smem_u32(sxn), gxn, E * F * 4, mbar);
    }

    // quarter-row weight slices for ALL 4 heads (cols w*128 + 4*lane)
    const int qoff = w * 128 + 4 * lane;
    float4 wn0 = ldg4(Wn + 0 * F + qoff);
    float4 wn1 = ldg4(Wn + 1 * F + qoff);
    float4 wn2 = ldg4(Wn + 2 * F + qoff);
    float4 wn3 = ldg4(Wn + 3 * F + qoff);

    {   // self logit partial (from global, while TMA lands)
        float4 xv = ldg4(gxs + qoff);
        float p0 = dot4(xv, ldg4(Ws + 0 * F + qoff), 0.f);
        float p1 = dot4(xv, ldg4(Ws + 1 * F + qoff), 0.f);
        float p2 = dot4(xv, ldg4(Ws + 2 * F + qoff), 0.f);
        float p3 = dot4(xv, ldg4(Ws + 3 * F + qoff), 0.f);
        float r = butterfly4(p0, p1, p2, p3, lane);
        if (lane < 4) sredS[w][lane] = r;
    }

    mbar_wait(mbar, 0);

    #pragma unroll
    for (int e = 0; e < E; e++) {
        float4 xv = lds4(&sxn[e * F + qoff]);
        float p0 = dot4(xv, wn0, 0.f);
        float p1 = dot4(xv, wn1, 0.f);
        float p2 = dot4(xv, wn2, 0.f);
        float p3 = dot4(xv, wn3, 0.f);
        float r = butterfly4(p0, p1, p2, p3, lane);
        if (lane < 4) sredN[e][w][lane] = r;
    }
    __syncthreads();

    {   // softmax per head (warp w = head); combine 4 warp-partials
        float es = sredS[0][w] + sredS[1][w] + sredS[2][w] + sredS[3][w];
        float v;
        if (lane < E) {
            float en = sredN[lane][0][w] + sredN[lane][1][w]
                     + sredN[lane][2][w] + sredN[lane][3][w];
            float l = es + en;
            v = (l >= 0.f) ? l : 0.2f * l;
        } else {
            v = -3.4e38f;
        }
        float m = v;
        #pragma unroll
        for (int o = 16; o; o >>= 1) m = fmaxf(m, __shfl_xor_sync(0xffffffffu, m, o));
        float p = (lane < E) ? __expf(v - m) : 0.f;
        float sum = p;
        #pragma unroll
        for (int o = 16; o; o >>= 1) sum += __shfl_xor_sync(0xffffffffu, sum, o);
        if (lane < E) salpha[lane * 4 + w] = p / sum;
    }
    __syncthreads();

    // aggregate with broadcast alpha LDS.128 (R14 form)
    float acc[4][4];
    #pragma unroll
    for (int c = 0; c < 4; c++)
        #pragma unroll
        for (int q = 0; q < 4; q++) acc[c][q] = 0.f;
    #pragma unroll
    for (int e = 0; e < E; e++) {
        float4 al = lds4(&salpha[e * 4]);
        #pragma unroll
        for (int c = 0; c < 4; c++) {
            float val = sxn[e * F + c * 128 + tid];
            acc[c][0] = fmaf(al.x, val, acc[c][0]);
            acc[c][1] = fmaf(al.y, val, acc[c][1]);
            acc[c][2] = fmaf(al.z, val, acc[c][2]);
            acc[c][3] = fmaf(al.w, val, acc[c][3]);
        }
    }
    float* gy = y + (size_t)g * (4 * F);
    #pragma unroll
    for (int q = 0; q < 4; q++)
        #pragma unroll
        for (int c = 0; c < 4; c++)
            gy[q * F + c * 128 + tid] = acc[c][q];
}

// ---------------------------------------------------------------------------
extern "C" void kernel_launch(void* const* d_in, const int* in_sizes, int n_in,
                              void* d_out, int out_size)
{
    const float* h0  = (const float*)d_in[0];
    const float* h1  = (const float*)d_in[1];
    const float* h2  = (const float*)d_in[2];
    const float* W0  = (const float*)d_in[3];
    const float* a0s = (const float*)d_in[4];
    const float* a0n = (const float*)d_in[5];
    const float* W1  = (const float*)d_in[6];
    const float* a1s = (const float*)d_in[7];
    const float* a1n = (const float*)d_in[8];
    const float* Wfc = (const float*)d_in[9];
    float* out = (float*)d_out;

    float* scr = nullptr;
    cudaGetSymbolAddress((void**)&scr, g_scratch);
    float* y1   = scr + OFF_Y1;
    float* y0   = scr + OFF_Y0;
    float* u    = scr + OFF_U;
    float* hs0  = scr + OFF_H;
    float* P0   = scr + OFF_P0;
    float* Q    = scr + OFF_Q;
    float* Nmat = scr + OFF_N;

    // fused prep: N tiles + Q (self-contained) + P0, one launch
    prep_kernel<<<276, 256>>>(W0, W1, a0s, a0n, a1s, a1n, Nmat, Q, P0);

    // both F=128 attentions
    attn128_kernel<<<10240 + 1024, 128>>>(h0, h1, h2, P0, P0 + 512,
                                          y1, y0, 10240);

    // layer-1 attention -> u [1024, 4(h'), 512]
    attn512_kernel<<<1024, 128>>>(y0, y1, Q, Q + 2048, u);

    // hs0[g, hp*128+d'] = u[g,hp,:] @ N[hp]
    gemm_kernel<<<dim3(2, 16, 4), dim3(16, 16)>>>(u, Nmat, hs0, 512, 2048, 128, 512,
                                                  512, 512 * 128, 128);
    // out = hs0 @ Wfc
    gemm_kernel<<<dim3(4, 16, 1), dim3(16, 16)>>>(hs0, Wfc, out, 512, 512, 256, 256,
                                                  0, 0, 0);
}

// round 17
// speedup vs baseline: 1.1477x; 1.1477x over previous
#include <cuda_runtime.h>
#include <cstdint>

// ---------------------------------------------------------------------------
// GAT hierarchical 2-layer. R17 = R15 (117.2us proven) with ONE change: the
// GEMM inner loop uses packed fma.rn.f32x2 (2 MACs/instr; FFMA rt_SMSP=2 made
// the 64x64 fp32 GEMMs issue-floor-bound at ~19us each). Exact same fp32 math.
// attn128 / attn512 / preps byte-identical to R15 (R16's changes reverted).
// ---------------------------------------------------------------------------

// scratch layout (floats)
static constexpr size_t OFF_Y1 = 0;                        // [10240,512]
static constexpr size_t OFF_Y0 = OFF_Y1 + 10240ull * 512;  // [1024,512]
static constexpr size_t OFF_U  = OFF_Y0 + 1024ull * 512;   // [1024,2048]
static constexpr size_t OFF_H  = OFF_U  + 1024ull * 2048;  // [1024,512]
static constexpr size_t OFF_P0 = OFF_H  + 1024ull * 512;   // P0s[512],P0n[512]
static constexpr size_t OFF_Q  = OFF_P0 + 1024;            // Qs[2048],Qn[2048]
static constexpr size_t OFF_N  = OFF_Q  + 4096;            // N[4][512][128]
static constexpr size_t SCRATCH_FLOATS = OFF_N + 4ull * 512 * 128;

__device__ float g_scratch[SCRATCH_FLOATS];

static __device__ __forceinline__ float4 ldg4(const float* p) {
    return __ldg((const float4*)p);
}
static __device__ __forceinline__ float dot4(float4 a, float4 b, float acc) {
    acc = fmaf(a.x, b.x, acc);
    acc = fmaf(a.y, b.y, acc);
    acc = fmaf(a.z, b.z, acc);
    acc = fmaf(a.w, b.w, acc);
    return acc;
}
static __device__ __forceinline__ uint32_t smem_u32(const void* p) {
    return (uint32_t)__cvta_generic_to_shared(p);
}
static __device__ __forceinline__ void mbar_init(uint32_t mbar, uint32_t cnt) {
    asm volatile("mbarrier.init.shared.b64 [%0], %1;" :: "r"(mbar), "r"(cnt) : "memory");
}
static __device__ __forceinline__ void mbar_expect_tx(uint32_t mbar, uint32_t bytes) {
    asm volatile("mbarrier.arrive.expect_tx.shared.b64 _, [%0], %1;"
                 :: "r"(mbar), "r"(bytes) : "memory");
}
static __device__ __forceinline__ void bulk_g2s(uint32_t dst, const void* src,
                                                uint32_t bytes, uint32_t mbar) {
    asm volatile("cp.async.bulk.shared::cluster.global.mbarrier::complete_tx::bytes "
                 "[%0], [%1], %2, [%3];"
                 :: "r"(dst), "l"(src), "r"(bytes), "r"(mbar) : "memory");
}
static __device__ __forceinline__ void mbar_wait(uint32_t mbar, uint32_t parity) {
    asm volatile(
        "{\n\t.reg .pred P;\n"
        "W_%=:\n\t"
        "mbarrier.try_wait.parity.shared.b64 P, [%0], %1;\n\t"
        "@P bra D_%=;\n\t"
        "bra W_%=;\n"
        "D_%=:\n\t}"
        :: "r"(mbar), "r"(parity) : "memory");
}
static __device__ __forceinline__ float4 lds4(const float* p) {
    float4 v;
    asm volatile("ld.shared.v4.f32 {%0,%1,%2,%3}, [%4];"
                 : "=f"(v.x), "=f"(v.y), "=f"(v.z), "=f"(v.w)
                 : "r"(smem_u32(p)));
    return v;
}

// butterfly multi-reduce (proven R10/R15)
static __device__ __forceinline__ float butterfly4(float p0, float p1,
                                                   float p2, float p3, int lane)
{
    bool b0 = (lane & 1);
    float send = b0 ? p0 : p1;
    float recv = __shfl_xor_sync(0xffffffffu, send, 1);
    float q01 = (b0 ? p1 : p0) + recv;
    send = b0 ? p2 : p3;
    recv = __shfl_xor_sync(0xffffffffu, send, 1);
    float q23 = (b0 ? p3 : p2) + recv;

    bool b1 = (lane & 2);
    send = b1 ? q01 : q23;
    recv = __shfl_xor_sync(0xffffffffu, send, 2);
    float r = (b1 ? q23 : q01) + recv;

    r += __shfl_xor_sync(0xffffffffu, r, 4);
    r += __shfl_xor_sync(0xffffffffu, r, 8);
    r += __shfl_xor_sync(0xffffffffu, r, 16);
    return r;
}

// ---------------------------------------------------------------------------
// prepN (32x32 tiles), byte-identical to R6/R15.
// ---------------------------------------------------------------------------
__global__ __launch_bounds__(256)
void prepN_kernel(const float* __restrict__ W0, const float* __restrict__ W1,
                  float* __restrict__ Nmat)
{
    const int z = blockIdx.z;
    const int hp = z >> 2, h = z & 3;
    const float* A = W0 + h * 128;
    const float* B = W1 + (size_t)(h * 128) * 512 + hp * 128;
    float* C = Nmat + (size_t)hp * 65536 + (size_t)(h * 128) * 128;

    const int M0 = blockIdx.y * 32;
    const int N0 = blockIdx.x * 32;
    const int tx = threadIdx.x & 15;
    const int ty = threadIdx.x >> 4;
    const int tid = threadIdx.x;

    __shared__ float As[16][32];
    __shared__ float Bs[16][32];

    float acc[2][2] = {{0.f, 0.f}, {0.f, 0.f}};

    for (int k0 = 0; k0 < 128; k0 += 16) {
        if (tid < 128) {
            int r = tid >> 2, c4 = (tid & 3) * 4;
            float4 av = *(const float4*)(A + (size_t)(M0 + r) * 512 + k0 + c4);
            As[c4 + 0][r] = av.x;
            As[c4 + 1][r] = av.y;
            As[c4 + 2][r] = av.z;
            As[c4 + 3][r] = av.w;
        } else {
            int t = tid - 128;
            int r = t >> 3, c4 = (t & 7) * 4;
            float4 bv = *(const float4*)(B + (size_t)(k0 + r) * 512 + N0 + c4);
            *(float4*)&Bs[r][c4] = bv;
        }
        __syncthreads();
        #pragma unroll
        for (int k = 0; k < 16; k++) {
            float a0 = As[k][ty * 2], a1 = As[k][ty * 2 + 1];
            float b0 = Bs[k][tx * 2], b1 = Bs[k][tx * 2 + 1];
            acc[0][0] = fmaf(a0, b0, acc[0][0]);
            acc[0][1] = fmaf(a0, b1, acc[0][1]);
            acc[1][0] = fmaf(a1, b0, acc[1][0]);
            acc[1][1] = fmaf(a1, b1, acc[1][1]);
        }
        __syncthreads();
    }
    #pragma unroll
    for (int i = 0; i < 2; i++)
        #pragma unroll
        for (int j = 0; j < 2; j++)
            C[(size_t)(M0 + ty * 2 + i) * 128 + N0 + tx * 2 + j] = acc[i][j];
}

// ---------------------------------------------------------------------------
// prepQP: Q = N @ a1 (exact) and P0 = W0_h @ a0. Byte-identical to R6/R15.
// ---------------------------------------------------------------------------
__global__ __launch_bounds__(128)
void prepQP_kernel(const float* __restrict__ Nmat,
                   const float* __restrict__ a1s, const float* __restrict__ a1n,
                   const float* __restrict__ W0,
                   const float* __restrict__ a0s, const float* __restrict__ a0n,
                   float* __restrict__ Q, float* __restrict__ P0)
{
    const int b = blockIdx.x;
    const int tid = threadIdx.x;
    if (b < 16) {
        const int hp = b >> 2, h = b & 3;
        __shared__ float sa1s[128], sa1n[128];
        sa1s[tid] = a1s[hp * 128 + tid];
        sa1n[tid] = a1n[hp * 128 + tid];
        __syncthreads();
        const float* nrow = Nmat + (size_t)hp * 65536 + (size_t)(h * 128 + tid) * 128;
        float s = 0.f, n = 0.f;
        #pragma unroll 4
        for (int d = 0; d < 128; d++) {
            float nv = nrow[d];
            s = fmaf(nv, sa1s[d], s);
            n = fmaf(nv, sa1n[d], n);
        }
        Q[hp * 512 + h * 128 + tid] = s;
        Q[2048 + hp * 512 + h * 128 + tid] = n;
    } else {
        const int t = (b - 16) * 128 + tid;
        const int h = t >> 7, f = t & 127;
        const float* wrow = W0 + (size_t)f * 512 + h * 128;
        const float* as = a0s + h * 128;
        const float* an = a0n + h * 128;
        float s = 0.f, n = 0.f;
        #pragma unroll 4
        for (int d = 0; d < 128; d++) {
            float wv = wrow[d];
            s = fmaf(wv, as[d], s);
            n = fmaf(wv, an[d], n);
        }
        P0[t] = s;
        P0[512 + t] = n;
    }
}

// ---------------------------------------------------------------------------
// fp32 GEMM: 64x64 tile, BK=16, 256 threads, 4x4/thread, reg double-buffer.
// NEW: inner loop uses packed fma.rn.f32x2 (2 MACs/instr).
// ---------------------------------------------------------------------------
__global__ __launch_bounds__(256)
void gemm_kernel(const float* __restrict__ A, const float* __restrict__ B,
                 float* __restrict__ C,
                 int K, int lda, int ldb, int ldc,
                 int offA, int offB, int offC)
{
    A += (size_t)blockIdx.z * offA;
    B += (size_t)blockIdx.z * offB;
    C += (size_t)blockIdx.z * offC;

    const int row0 = blockIdx.y * 64;
    const int col0 = blockIdx.x * 64;
    const int tx = threadIdx.x;
    const int ty = threadIdx.y;
    const int tid = ty * 16 + tx;

    __shared__ float As[16][64];
    __shared__ float Bs[16][64];

    const int ar = tid >> 2;
    const int ac = (tid & 3) * 4;
    const int br = tid >> 4;
    const int bc = (tid & 15) * 4;

    // accumulators packed as f32x2 pairs: acc01[i] = {C[i][0],C[i][1]}, etc.
    unsigned long long acc01[4], acc23[4];
    #pragma unroll
    for (int i = 0; i < 4; i++) { acc01[i] = 0ull; acc23[i] = 0ull; }

    const int nt = K >> 4;
    float4 av = *(const float4*)(A + (size_t)(row0 + ar) * lda + ac);
    float4 bv = *(const float4*)(B + (size_t)br * ldb + col0 + bc);

    for (int i = 0; i < nt; i++) {
        As[ac + 0][ar] = av.x;
        As[ac + 1][ar] = av.y;
        As[ac + 2][ar] = av.z;
        As[ac + 3][ar] = av.w;
        *(float4*)&Bs[br][bc] = bv;
        __syncthreads();

        if (i + 1 < nt) {
            int k0 = (i + 1) << 4;
            av = *(const float4*)(A + (size_t)(row0 + ar) * lda + k0 + ac);
            bv = *(const float4*)(B + (size_t)(k0 + br) * ldb + col0 + bc);
        }

        #pragma unroll
        for (int k = 0; k < 16; k++) {
            float4 a4 = *(const float4*)&As[k][ty * 4];
            float4 b4 = *(const float4*)&Bs[k][tx * 4];
            unsigned long long b01, b23;
            asm("mov.b64 %0, {%1, %2};" : "=l"(b01) : "f"(b4.x), "f"(b4.y));
            asm("mov.b64 %0, {%1, %2};" : "=l"(b23) : "f"(b4.z), "f"(b4.w));
            float a[4] = {a4.x, a4.y, a4.z, a4.w};
            #pragma unroll
            for (int ii = 0; ii < 4; ii++) {
                unsigned long long ai;
                asm("mov.b64 %0, {%1, %1};" : "=l"(ai) : "f"(a[ii]));
                asm("fma.rn.f32x2 %0, %1, %2, %0;" : "+l"(acc01[ii]) : "l"(ai), "l"(b01));
                asm("fma.rn.f32x2 %0, %1, %2, %0;" : "+l"(acc23[ii]) : "l"(ai), "l"(b23));
            }
        }
        __syncthreads();
    }

    #pragma unroll
    for (int i = 0; i < 4; i++) {
        float o0, o1, o2, o3;
        asm("mov.b64 {%0, %1}, %2;" : "=f"(o0), "=f"(o1) : "l"(acc01[i]));
        asm("mov.b64 {%0, %1}, %2;" : "=f"(o2), "=f"(o3) : "l"(acc23[i]));
        float4 o = {o0, o1, o2, o3};
        *(float4*)(C + (size_t)(row0 + ty * 4 + i) * ldc + col0 + tx * 4) = o;
    }
}

// ---------------------------------------------------------------------------
// F=128 attention, both levels fused. Byte-identical to R15 (the winner).
// ---------------------------------------------------------------------------
__global__ __launch_bounds__(128)
void attn128_kernel(const float* __restrict__ h0, const float* __restrict__ h1,
                    const float* __restrict__ h2,
                    const float* __restrict__ Ws, const float* __restrict__ Wn,
                    float* __restrict__ y1, float* __restrict__ y0, int G1)
{
    __shared__ float sxn[25 * 128];
    __shared__ float slog[26 * 4];
    __shared__ float salpha[25 * 4];
    __shared__ uint64_t mbar_s;

    const int b = blockIdx.x;
    const bool big = b < G1;
    const int g = big ? b : b - G1;
    const int E = big ? 25 : 10;
    const float* gxn = big ? (h2 + (size_t)g * 25 * 128) : (h1 + (size_t)g * 10 * 128);
    const float* gxs = big ? (h1 + (size_t)g * 128) : (h0 + (size_t)g * 128);
    float* gy = (big ? y1 : y0) + (size_t)g * 512;

    const int tid  = threadIdx.x;
    const int w    = tid >> 5;
    const int lane = tid & 31;
    const uint32_t mbar = smem_u32(&mbar_s);

    if (tid == 0) {
        mbar_init(mbar, 1);
        asm volatile("fence.proxy.async.shared::cta;" ::: "memory");
    }
    __syncthreads();
    if (tid == 0) {
        mbar_expect_tx(mbar, (uint32_t)(E * 128 * 4));
        bulk_g2s(smem_u32(sxn), gxn, (uint32_t)(E * 128 * 4), mbar);
    }

    float4 wn0 = ldg4(Wn + 0 * 128 + 4 * lane);
    float4 wn1 = ldg4(Wn + 1 * 128 + 4 * lane);
    float4 wn2 = ldg4(Wn + 2 * 128 + 4 * lane);
    float4 wn3 = ldg4(Wn + 3 * 128 + 4 * lane);

    if (w == 0) {
        float4 xv = ldg4(gxs + 4 * lane);
        float p0 = dot4(xv, ldg4(Ws + 0 * 128 + 4 * lane), 0.f);
        float p1 = dot4(xv, ldg4(Ws + 1 * 128 + 4 * lane), 0.f);
        float p2 = dot4(xv, ldg4(Ws + 2 * 128 + 4 * lane), 0.f);
        float p3 = dot4(xv, ldg4(Ws + 3 * 128 + 4 * lane), 0.f);
        float r = butterfly4(p0, p1, p2, p3, lane);
        if (lane < 4) slog[E * 4 + lane] = r;
    }

    mbar_wait(mbar, 0);

    for (int e = w; e < E; e += 4) {
        float4 xv = lds4(&sxn[e * 128 + 4 * lane]);
        float p0 = dot4(xv, wn0, 0.f);
        float p1 = dot4(xv, wn1, 0.f);
        float p2 = dot4(xv, wn2, 0.f);
        float p3 = dot4(xv, wn3, 0.f);
        float r = butterfly4(p0, p1, p2, p3, lane);
        if (lane < 4) slog[e * 4 + lane] = r;
    }
    __syncthreads();

    {
        float es = slog[E * 4 + w];
        float v;
        if (lane < E) {
            float l = es + slog[lane * 4 + w];
            v = (l >= 0.f) ? l : 0.2f * l;
        } else {
            v = -3.4e38f;
        }
        float m = v;
        #pragma unroll
        for (int o = 16; o; o >>= 1) m = fmaxf(m, __shfl_xor_sync(0xffffffffu, m, o));
        float p = (lane < E) ? __expf(v - m) : 0.f;
        float sum = p;
        #pragma unroll
        for (int o = 16; o; o >>= 1) sum += __shfl_xor_sync(0xffffffffu, sum, o);
        if (lane < E) salpha[lane * 4 + w] = p / sum;
    }
    __syncthreads();

    float acc0 = 0.f, acc1 = 0.f, acc2 = 0.f, acc3 = 0.f;
    for (int e = 0; e < E; e++) {
        float4 al = lds4(&salpha[e * 4]);
        float val = sxn[e * 128 + tid];
        acc0 = fmaf(al.x, val, acc0);
        acc1 = fmaf(al.y, val, acc1);
        acc2 = fmaf(al.z, val, acc2);
        acc3 = fmaf(al.w, val, acc3);
    }
    gy[0 * 128 + tid] = acc0;
    gy[1 * 128 + tid] = acc1;
    gy[2 * 128 + tid] = acc2;
    gy[3 * 128 + tid] = acc3;
}

// ---------------------------------------------------------------------------
// F=512, E=10 attention: byte-identical to R14/R15.
// ---------------------------------------------------------------------------
__global__ __launch_bounds__(128)
void attn512_kernel(const float* __restrict__ xs, const float* __restrict__ xn,
                    const float* __restrict__ Ws, const float* __restrict__ Wn,
                    float* __restrict__ y)
{
    constexpr int E = 10, F = 512;
    __shared__ float sxn[E * F];
    __shared__ float slog[(E + 1) * 4];
    __shared__ float salpha[E * 4];
    __shared__ uint64_t mbar_s;

    const int g    = blockIdx.x;
    const int tid  = threadIdx.x;
    const int w    = tid >> 5;
    const int lane = tid & 31;
    const uint32_t mbar = smem_u32(&mbar_s);
    const float* gxn = xn + (size_t)g * E * F;
    const float* gxs = xs + (size_t)g * F;

    if (tid == 0) {
        mbar_init(mbar, 1);
        asm volatile("fence.proxy.async.shared::cta;" ::: "memory");
    }
    __syncthreads();
    if (tid == 0) {
        mbar_expect_tx(mbar, E * F * 4);
        bulk_g2s(smem_u32(sxn), gxn, E * F * 4, mbar);
    }

    float4 wq[4], wsq[4];
    #pragma unroll
    for (int j = 0; j < 4; j++) {
        wq[j]  = ldg4(Wn + w * F + 4 * (lane + 32 * j));
        wsq[j] = ldg4(Ws + w * F + 4 * (lane + 32 * j));
    }

    {
        float acc = 0.f;
        #pragma unroll
        for (int j = 0; j < 4; j++)
            acc = dot4(ldg4(gxs + 4 * (lane + 32 * j)), wsq[j], acc);
        #pragma unroll
        for (int o = 16; o; o >>= 1) acc += __shfl_xor_sync(0xffffffffu, acc, o);
        if (lane == 0) slog[E * 4 + w] = acc;
    }

    mbar_wait(mbar, 0);

    for (int e = 0; e < E; e++) {
        const float* xp = &sxn[e * F];
        float acc = 0.f;
        #pragma unroll
        for (int j = 0; j < 4; j++)
            acc = dot4(lds4(xp + 4 * (lane + 32 * j)), wq[j], acc);
        #pragma unroll
        for (int o = 16; o; o >>= 1) acc += __shfl_xor_sync(0xffffffffu, acc, o);
        if (lane == 0) slog[e * 4 + w] = acc;
    }
    __syncthreads();

    {
        float es = slog[E * 4 + w];
        float v;
        if (lane < E) {
            float l = es + slog[lane * 4 + w];
            v = (l >= 0.f) ? l : 0.2f * l;
        } else {
            v = -3.4e38f;
        }
        float m = v;
        #pragma unroll
        for (int o = 16; o; o >>= 1) m = fmaxf(m, __shfl_xor_sync(0xffffffffu, m, o));
        float p = (lane < E) ? __expf(v - m) : 0.f;
        float sum = p;
        #pragma unroll
        for (int o = 16; o; o >>= 1) sum += __shfl_xor_sync(0xffffffffu, sum, o);
        if (lane < E) salpha[lane * 4 + w] = p / sum;
    }
    __syncthreads();

    float acc[4][4];
    #pragma unroll
    for (int c = 0; c < 4; c++)
        #pragma unroll
        for (int q = 0; q < 4; q++) acc[c][q] = 0.f;
    #pragma unroll
    for (int e = 0; e < E; e++) {
        float4 al = lds4(&salpha[e * 4]);
        #pragma unroll
        for (int c = 0; c < 4; c++) {
            float val = sxn[e * F + c * 128 + tid];
            acc[c][0] = fmaf(al.x, val, acc[c][0]);
            acc[c][1] = fmaf(al.y, val, acc[c][1]);
            acc[c][2] = fmaf(al.z, val, acc[c][2]);
            acc[c][3] = fmaf(al.w, val, acc[c][3]);
        }
    }
    float* gy = y + (size_t)g * (4 * F);
    #pragma unroll
    for (int q = 0; q < 4; q++)
        #pragma unroll
        for (int c = 0; c < 4; c++)
            gy[q * F + c * 128 + tid] = acc[c][q];
}

// ---------------------------------------------------------------------------
extern "C" void kernel_launch(void* const* d_in, const int* in_sizes, int n_in,
                              void* d_out, int out_size)
{
    const float* h0  = (const float*)d_in[0];
    const float* h1  = (const float*)d_in[1];
    const float* h2  = (const float*)d_in[2];
    const float* W0  = (const float*)d_in[3];
    const float* a0s = (const float*)d_in[4];
    const float* a0n = (const float*)d_in[5];
    const float* W1  = (const float*)d_in[6];
    const float* a1s = (const float*)d_in[7];
    const float* a1n = (const float*)d_in[8];
    const float* Wfc = (const float*)d_in[9];
    float* out = (float*)d_out;

    float* scr = nullptr;
    cudaGetSymbolAddress((void**)&scr, g_scratch);
    float* y1   = scr + OFF_Y1;
    float* y0   = scr + OFF_Y0;
    float* u    = scr + OFF_U;
    float* hs0  = scr + OFF_H;
    float* P0   = scr + OFF_P0;
    float* Q    = scr + OFF_Q;
    float* Nmat = scr + OFF_N;

    prepN_kernel<<<dim3(4, 4, 16), 256>>>(W0, W1, Nmat);
    prepQP_kernel<<<20, 128>>>(Nmat, a1s, a1n, W0, a0s, a0n, Q, P0);

    // both F=128 attentions
    attn128_kernel<<<10240 + 1024, 128>>>(h0, h1, h2, P0, P0 + 512,
                                          y1, y0, 10240);

    // layer-1 attention -> u [1024, 4(h'), 512]
    attn512_kernel<<<1024, 128>>>(y0, y1, Q, Q + 2048, u);

    // hs0[g, hp*128+d'] = u[g,hp,:] @ N[hp]
    gemm_kernel<<<dim3(2, 16, 4), dim3(16, 16)>>>(u, Nmat, hs0, 512, 2048, 128, 512,
                                                  512, 512 * 128, 128);
    // out = hs0 @ Wfc
    gemm_kernel<<<dim3(4, 16, 1), dim3(16, 16)>>>(hs0, Wfc, out, 512, 512, 256, 256,
                                                  0, 0, 0);
}